// round 7
// baseline (speedup 1.0000x reference)
#include <cuda_runtime.h>
#include <cuda_bf16.h>
#include <cstdint>

// Problem constants (shapes fixed by the dataset)
#define N_NODES_MAX 100000
#define D 64
#define OUT 64
#define LN_EPS 1e-5f

// Scratch: neighbor_sum accumulator [N, D] — device global (no allocs allowed)
__device__ __align__(16) float g_nsum[N_NODES_MAX * D];
__device__ int g_is64;  // 1 if edge_index is int64, 0 if int32

// ---------------------------------------------------------------------------
// Kernel 0: zero the accumulator + (block 0) parallel dtype detection.
// ---------------------------------------------------------------------------
__global__ void zero_detect_kernel(int n_float4,
                                   const long long* __restrict__ ei,
                                   int n_words, int n_nodes) {
    if (blockIdx.x == 0) {
        int bad = 0;
        int i = threadIdx.x;
        if (i < n_words) {
            long long v = ei[i];
            bad = (v < 0 || v >= (long long)n_nodes) ? 1 : 0;
        }
        int any_bad = __syncthreads_or(bad);
        if (threadIdx.x == 0) g_is64 = any_bad ? 0 : 1;
    }
    int i = blockIdx.x * blockDim.x + threadIdx.x;
    int stride = gridDim.x * blockDim.x;
    float4* p = reinterpret_cast<float4*>(g_nsum);
    float4 z = make_float4(0.f, 0.f, 0.f, 0.f);
    for (; i < n_float4; i += stride) p[i] = z;
}

// ---------------------------------------------------------------------------
// Kernel 1: scatter-add. 16 lanes per edge; lane handles float4 chunk `sub`.
// red.global.add.v4.f32: 4 floats per instruction, no return value.
// ---------------------------------------------------------------------------
__global__ void __launch_bounds__(256) scatter_kernel(
    const float4* __restrict__ x4,
    const void* __restrict__ ei_raw,
    int n_edges) {

    const long long* ei64 = reinterpret_cast<const long long*>(ei_raw);
    const int*       ei32 = reinterpret_cast<const int*>(ei_raw);
    const int is64 = g_is64;

    const int t   = blockIdx.x * blockDim.x + threadIdx.x;
    const int sub = t & 15;
    int e = t >> 4;
    const int estride = (gridDim.x * blockDim.x) >> 4;
    float4* __restrict__ nsum4 = reinterpret_cast<float4*>(g_nsum);

    if (is64) {
        for (; e < n_edges; e += estride) {
            long long row = ei64[e];
            long long col = ei64[n_edges + e];
            float4 v = x4[row * 16 + sub];
            float4* dst = &nsum4[col * 16 + sub];
            asm volatile("red.global.add.v4.f32 [%0], {%1, %2, %3, %4};"
                         :: "l"(dst), "f"(v.x), "f"(v.y), "f"(v.z), "f"(v.w)
                         : "memory");
        }
    } else {
        for (; e < n_edges; e += estride) {
            long long row = ei32[e];
            long long col = ei32[n_edges + e];
            float4 v = x4[row * 16 + sub];
            float4* dst = &nsum4[col * 16 + sub];
            asm volatile("red.global.add.v4.f32 [%0], {%1, %2, %3, %4};"
                         :: "l"(dst), "f"(v.x), "f"(v.y), "f"(v.z), "f"(v.w)
                         : "memory");
        }
    }
}

// ---------------------------------------------------------------------------
// Kernel 2: fused concat + Linear(128->64) + bias + LayerNorm.
// block = 64 nodes x 64 outs, 256 threads, thread tile = 4 nodes x 4 outs.
// A staged transposed AND PRE-DUPLICATED: Ash_dup[k][n] = {a, a} (8B each),
// so the k-loop reads broadcast-ready f32x2 operands straight from LDS —
// no mov.b64 duplication in the hot loop.
// W staged as f32x2 pairs over OUT (32KB).
// Inner loop per k per thread (16 FMA lanes in 11 issue slots):
//   2x LDS.128 (a-dups, dedup to 2x16B lines/warp)
//   1x LDS.128 (w: 2 f32x2 pairs)
//   8x fma.rn.f32x2
// smem: A_dup 64KB + W 32KB = 96KB -> 2 blocks/SM.
// acc layout identical to the proven R2 kernel.
// ---------------------------------------------------------------------------
#define TILE_N 64
#define NTHR   256

__global__ void __launch_bounds__(NTHR, 2) gemm_ln_kernel(
    const float4* __restrict__ x4,
    const float*  __restrict__ W,
    const float*  __restrict__ b,
    const float*  __restrict__ gamma,
    const float*  __restrict__ beta,
    float4* __restrict__ out4,
    int n_nodes) {

    extern __shared__ char smem_raw[];
    // A_dup: [128][64] pairs of identical floats (8B each) = 64KB
    float2* Adup = reinterpret_cast<float2*>(smem_raw);
    // W pairs: [128][32] f32x2 over OUT = 32KB
    unsigned long long* Wp =
        reinterpret_cast<unsigned long long*>(smem_raw + 128 * 64 * 8);

    const int tid = threadIdx.x;
    const int tx  = tid & 15;   // out-pair group: pairs {2tx,2tx+1} -> outs 4tx..4tx+3
    const int ty  = tid >> 4;   // node group: nodes 4ty..4ty+3  (ty 0..15)
    const int node_base = blockIdx.x * TILE_N;

    // stage W (row-major [128][64] floats == [128][32] f32x2 pairs)
    {
        const float4* W4  = reinterpret_cast<const float4*>(W);
        float4* Wp4 = reinterpret_cast<float4*>(Wp);
        #pragma unroll
        for (int i = tid; i < 128 * 64 / 4; i += NTHR) Wp4[i] = W4[i];
    }

    // stage A transposed + duplicated: Adup[k*64 + n] = {v, v}
    // where v = concat(x, nsum)[node_base+n][k]
    {
        const float4* nsum4 = reinterpret_cast<const float4*>(g_nsum);
        #pragma unroll
        for (int it = 0; it < 8; it++) {
            int idx = it * NTHR + tid;       // 0..2047
            int n = idx & 63;                // node within tile
            int r = idx >> 6;                // k-quad 0..31
            int gn = node_base + n;
            float4 v = make_float4(0.f, 0.f, 0.f, 0.f);
            if (gn < n_nodes)
                v = (r < 16) ? x4[(long long)gn * 16 + r]
                             : nsum4[(long long)gn * 16 + (r - 16)];
            int k0 = 4 * r;
            Adup[(k0 + 0) * 64 + n] = make_float2(v.x, v.x);
            Adup[(k0 + 1) * 64 + n] = make_float2(v.y, v.y);
            Adup[(k0 + 2) * 64 + n] = make_float2(v.z, v.z);
            Adup[(k0 + 3) * 64 + n] = make_float2(v.w, v.w);
        }
    }
    __syncthreads();

    unsigned long long acc[4][2];
    #pragma unroll
    for (int i = 0; i < 4; i++) { acc[i][0] = 0ull; acc[i][1] = 0ull; }

    const unsigned long long* ab =
        reinterpret_cast<const unsigned long long*>(Adup) + 4 * ty;
    const unsigned long long* wb = Wp + 2 * tx;

    #pragma unroll 8
    for (int k = 0; k < 128; k++) {
        // 4 duplicated a-pairs for this thread's 4 nodes (32B, two LDS.128)
        ulonglong2 a01 = *reinterpret_cast<const ulonglong2*>(ab + k * 64);
        ulonglong2 a23 = *reinterpret_cast<const ulonglong2*>(ab + k * 64 + 2);
        ulonglong2 w   = *reinterpret_cast<const ulonglong2*>(wb + k * 32);
        asm("fma.rn.f32x2 %0, %1, %2, %0;" : "+l"(acc[0][0]) : "l"(a01.x), "l"(w.x));
        asm("fma.rn.f32x2 %0, %1, %2, %0;" : "+l"(acc[0][1]) : "l"(a01.x), "l"(w.y));
        asm("fma.rn.f32x2 %0, %1, %2, %0;" : "+l"(acc[1][0]) : "l"(a01.y), "l"(w.x));
        asm("fma.rn.f32x2 %0, %1, %2, %0;" : "+l"(acc[1][1]) : "l"(a01.y), "l"(w.y));
        asm("fma.rn.f32x2 %0, %1, %2, %0;" : "+l"(acc[2][0]) : "l"(a23.x), "l"(w.x));
        asm("fma.rn.f32x2 %0, %1, %2, %0;" : "+l"(acc[2][1]) : "l"(a23.x), "l"(w.y));
        asm("fma.rn.f32x2 %0, %1, %2, %0;" : "+l"(acc[3][0]) : "l"(a23.y), "l"(w.x));
        asm("fma.rn.f32x2 %0, %1, %2, %0;" : "+l"(acc[3][1]) : "l"(a23.y), "l"(w.y));
    }

    // epilogue: bias + LayerNorm + store (identical to proven R2)
    const float4 bj = reinterpret_cast<const float4*>(b)[tx];
    const float4 gj = reinterpret_cast<const float4*>(gamma)[tx];
    const float4 ej = reinterpret_cast<const float4*>(beta)[tx];

    float val[4][4];
    #pragma unroll
    for (int i = 0; i < 4; i++) {
        val[i][0] = __uint_as_float((unsigned)(acc[i][0] & 0xffffffffull)) + bj.x;
        val[i][1] = __uint_as_float((unsigned)(acc[i][0] >> 32))           + bj.y;
        val[i][2] = __uint_as_float((unsigned)(acc[i][1] & 0xffffffffull)) + bj.z;
        val[i][3] = __uint_as_float((unsigned)(acc[i][1] >> 32))           + bj.w;
    }

    float s[4], ss[4];
    #pragma unroll
    for (int i = 0; i < 4; i++) {
        s[i]  = val[i][0] + val[i][1] + val[i][2] + val[i][3];
        ss[i] = val[i][0] * val[i][0] + val[i][1] * val[i][1]
              + val[i][2] * val[i][2] + val[i][3] * val[i][3];
    }
    // reduce across the 16 tx lanes (xor masks stay inside each 16-lane half)
    #pragma unroll
    for (int m = 1; m < 16; m <<= 1) {
        #pragma unroll
        for (int i = 0; i < 4; i++) {
            s[i]  += __shfl_xor_sync(0xFFFFFFFFu, s[i],  m);
            ss[i] += __shfl_xor_sync(0xFFFFFFFFu, ss[i], m);
        }
    }

    const float inv64 = 1.0f / 64.0f;
    #pragma unroll
    for (int i = 0; i < 4; i++) {
        float mu  = s[i] * inv64;
        float var = ss[i] * inv64 - mu * mu;
        float rs  = rsqrtf(var + LN_EPS);
        int gn = node_base + 4 * ty + i;
        if (gn < n_nodes) {
            float4 o;
            o.x = (val[i][0] - mu) * rs * gj.x + ej.x;
            o.y = (val[i][1] - mu) * rs * gj.y + ej.y;
            o.z = (val[i][2] - mu) * rs * gj.z + ej.z;
            o.w = (val[i][3] - mu) * rs * gj.w + ej.w;
            out4[(long long)gn * 16 + tx] = o;
        }
    }
}

// ---------------------------------------------------------------------------
// launch
// ---------------------------------------------------------------------------
extern "C" void kernel_launch(void* const* d_in, const int* in_sizes, int n_in,
                              void* d_out, int out_size) {
    const float* x     = (const float*)d_in[0];
    const void*  ei    = d_in[1];
    const float* W     = (const float*)d_in[2];
    const float* b     = (const float*)d_in[3];
    const float* gamma = (const float*)d_in[4];
    const float* beta  = (const float*)d_in[5];
    float* out = (float*)d_out;

    const int n_nodes = in_sizes[0] / D;      // 100000
    const int n_edges = in_sizes[1] / 2;      // 1000000

    // dynamic smem: A_dup (64KB) + W pairs (32KB) = 96KB
    static_assert(128 * 64 * 8 + 128 * 32 * 8 == 98304, "smem layout");
    cudaFuncSetAttribute(gemm_ln_kernel,
                         cudaFuncAttributeMaxDynamicSharedMemorySize, 98304);

    // 0: zero accumulator + parallel dtype detection (block 0)
    int n_words = n_edges / 2;
    if (n_words > 256) n_words = 256;
    const int n_f4 = n_nodes * D / 4;
    zero_detect_kernel<<<1184, 256>>>(n_f4, (const long long*)ei, n_words, n_nodes);

    // 1: scatter (16 lanes/edge, vectorized red.v4)
    scatter_kernel<<<2368, 256>>>((const float4*)x, ei, n_edges);

    // 2: fused GEMM + LayerNorm (pre-duplicated A, mov-free FFMA2 loop)
    int gemm_blocks = (n_nodes + TILE_N - 1) / TILE_N;
    gemm_ln_kernel<<<gemm_blocks, NTHR, 98304>>>(
        (const float4*)x, W, b, gamma, beta, (float4*)out, n_nodes);
}

// round 8
// speedup vs baseline: 1.1873x; 1.1873x over previous
#include <cuda_runtime.h>
#include <cuda_bf16.h>
#include <cstdint>

// Problem constants (shapes fixed by the dataset)
#define N_NODES_MAX 100000
#define D 64
#define OUT 64
#define LN_EPS 1e-5f

// Scratch: neighbor_sum accumulator [N, D] — device global (no allocs allowed)
__device__ __align__(16) float g_nsum[N_NODES_MAX * D];
__device__ int g_is64;  // 1 if edge_index is int64, 0 if int32

// ---------------------------------------------------------------------------
// Kernel 0: zero the accumulator + (block 0) parallel dtype detection.
// ---------------------------------------------------------------------------
__global__ void zero_detect_kernel(int n_float4,
                                   const long long* __restrict__ ei,
                                   int n_words, int n_nodes) {
    if (blockIdx.x == 0) {
        int bad = 0;
        int i = threadIdx.x;
        if (i < n_words) {
            long long v = ei[i];
            bad = (v < 0 || v >= (long long)n_nodes) ? 1 : 0;
        }
        int any_bad = __syncthreads_or(bad);
        if (threadIdx.x == 0) g_is64 = any_bad ? 0 : 1;
    }
    int i = blockIdx.x * blockDim.x + threadIdx.x;
    int stride = gridDim.x * blockDim.x;
    float4* p = reinterpret_cast<float4*>(g_nsum);
    float4 z = make_float4(0.f, 0.f, 0.f, 0.f);
    for (; i < n_float4; i += stride) p[i] = z;
}

// ---------------------------------------------------------------------------
// Kernel 1: scatter-add. 16 lanes per edge; lane handles float4 chunk `sub`.
// red.global.add.v4.f32: 4 floats per instruction, no return value.
// ---------------------------------------------------------------------------
__global__ void __launch_bounds__(256) scatter_kernel(
    const float4* __restrict__ x4,
    const void* __restrict__ ei_raw,
    int n_edges) {

    const long long* ei64 = reinterpret_cast<const long long*>(ei_raw);
    const int*       ei32 = reinterpret_cast<const int*>(ei_raw);
    const int is64 = g_is64;

    const int t   = blockIdx.x * blockDim.x + threadIdx.x;
    const int sub = t & 15;
    int e = t >> 4;
    const int estride = (gridDim.x * blockDim.x) >> 4;
    float4* __restrict__ nsum4 = reinterpret_cast<float4*>(g_nsum);

    if (is64) {
        for (; e < n_edges; e += estride) {
            long long row = ei64[e];
            long long col = ei64[n_edges + e];
            float4 v = x4[row * 16 + sub];
            float4* dst = &nsum4[col * 16 + sub];
            asm volatile("red.global.add.v4.f32 [%0], {%1, %2, %3, %4};"
                         :: "l"(dst), "f"(v.x), "f"(v.y), "f"(v.z), "f"(v.w)
                         : "memory");
        }
    } else {
        for (; e < n_edges; e += estride) {
            long long row = ei32[e];
            long long col = ei32[n_edges + e];
            float4 v = x4[row * 16 + sub];
            float4* dst = &nsum4[col * 16 + sub];
            asm volatile("red.global.add.v4.f32 [%0], {%1, %2, %3, %4};"
                         :: "l"(dst), "f"(v.x), "f"(v.y), "f"(v.z), "f"(v.w)
                         : "memory");
        }
    }
}

// ---------------------------------------------------------------------------
// Kernel 2: fused concat + Linear(128->64) + bias + LayerNorm.
// R4's node-packed register tiling, WITHOUT the RMW clear (which was proven
// to be the sole cause of the R4/R5 regressions).
//   block = 128 nodes x 64 outs, 256 threads, thread tile = 8 nodes x 4 outs.
// f32x2 packing over NODES: a-pairs come straight out of LDS.128 (no dup
// movs); only the 4 W scalars are duplicated per k (4x mov.b64).
// Inner loop per k per thread: 3x LDS.128 + 4x mov.b64 + 16x fma.rn.f32x2
//   = 27 issue slots for 32 FMA lanes.
// ---------------------------------------------------------------------------
#define TILE_N 128
#define NTHR   256

__global__ void __launch_bounds__(NTHR, 2) gemm_ln_kernel(
    const float4* __restrict__ x4,
    const float*  __restrict__ W,
    const float*  __restrict__ b,
    const float*  __restrict__ gamma,
    const float*  __restrict__ beta,
    float4* __restrict__ out4,
    int n_nodes) {

    extern __shared__ char smem_raw[];
    float* Ash = reinterpret_cast<float*>(smem_raw);             // [128][128]
    float* Wsh = reinterpret_cast<float*>(smem_raw + 128 * 128 * 4); // [128][64]

    const int tid = threadIdx.x;
    const int tx  = tid & 15;   // outs 4tx..4tx+3
    const int ty  = tid >> 4;   // nodes 8ty..8ty+7
    const int node_base = blockIdx.x * TILE_N;

    // stage W (row-major [128][64])
    {
        const float4* W4 = reinterpret_cast<const float4*>(W);
        float4* Wsh4 = reinterpret_cast<float4*>(Wsh);
        #pragma unroll
        for (int i = tid; i < 128 * 64 / 4; i += NTHR) Wsh4[i] = W4[i];
    }

    // stage A transposed: Ash[k][n] = concat(x, nsum)[node_base+n][k]
    // (pure reads — no RMW)
    {
        const float4* nsum4 = reinterpret_cast<const float4*>(g_nsum);
        #pragma unroll
        for (int it = 0; it < 16; it++) {
            int idx = it * NTHR + tid;
            int n = idx & 127;         // lanes consecutive in n -> STS conflict-free
            int r = idx >> 7;          // k-quad 0..31
            int gn = node_base + n;
            float4 v = make_float4(0.f, 0.f, 0.f, 0.f);
            if (gn < n_nodes)
                v = (r < 16) ? x4[(long long)gn * 16 + r]
                             : nsum4[(long long)gn * 16 + (r - 16)];
            int k0 = 4 * r;
            Ash[(k0 + 0) * 128 + n] = v.x;
            Ash[(k0 + 1) * 128 + n] = v.y;
            Ash[(k0 + 2) * 128 + n] = v.z;
            Ash[(k0 + 3) * 128 + n] = v.w;
        }
    }
    __syncthreads();

    // acc[i][j]: node-pair i (nodes 2i,2i+1 of this thread's 8) x out j
    unsigned long long acc[4][4];
    #pragma unroll
    for (int i = 0; i < 4; i++)
        #pragma unroll
        for (int j = 0; j < 4; j++) acc[i][j] = 0ull;

    const unsigned long long* ab =
        reinterpret_cast<const unsigned long long*>(Ash + 8 * ty);
    const float* wb = Wsh + 4 * tx;

    #pragma unroll 8
    for (int k = 0; k < 128; k++) {
        // 4 node-pairs, naturally packed (adjacent floats in Ash row)
        ulonglong2 a01 = *reinterpret_cast<const ulonglong2*>(ab + k * 64);
        ulonglong2 a23 = *reinterpret_cast<const ulonglong2*>(ab + k * 64 + 2);
        float4 wv = *reinterpret_cast<const float4*>(wb + k * 64);
        unsigned long long wd[4];
        asm("mov.b64 %0, {%1, %1};" : "=l"(wd[0]) : "f"(wv.x));
        asm("mov.b64 %0, {%1, %1};" : "=l"(wd[1]) : "f"(wv.y));
        asm("mov.b64 %0, {%1, %1};" : "=l"(wd[2]) : "f"(wv.z));
        asm("mov.b64 %0, {%1, %1};" : "=l"(wd[3]) : "f"(wv.w));
        unsigned long long ap[4] = {a01.x, a01.y, a23.x, a23.y};
        #pragma unroll
        for (int i = 0; i < 4; i++) {
            asm("fma.rn.f32x2 %0, %1, %2, %0;" : "+l"(acc[i][0]) : "l"(ap[i]), "l"(wd[0]));
            asm("fma.rn.f32x2 %0, %1, %2, %0;" : "+l"(acc[i][1]) : "l"(ap[i]), "l"(wd[1]));
            asm("fma.rn.f32x2 %0, %1, %2, %0;" : "+l"(acc[i][2]) : "l"(ap[i]), "l"(wd[2]));
            asm("fma.rn.f32x2 %0, %1, %2, %0;" : "+l"(acc[i][3]) : "l"(ap[i]), "l"(wd[3]));
        }
    }

    // epilogue: unpack (node 2i+di, out j), bias + LayerNorm + store
    // (identical to R4's validated epilogue)
    const float4 bj = reinterpret_cast<const float4*>(b)[tx];
    const float4 gj = reinterpret_cast<const float4*>(gamma)[tx];
    const float4 ej = reinterpret_cast<const float4*>(beta)[tx];
    const float bja[4] = {bj.x, bj.y, bj.z, bj.w};

    float val[8][4];   // [node 0..7][out 0..3]
    #pragma unroll
    for (int i = 0; i < 4; i++)
        #pragma unroll
        for (int j = 0; j < 4; j++) {
            val[2 * i][j]     = __uint_as_float((unsigned)(acc[i][j] & 0xffffffffull)) + bja[j];
            val[2 * i + 1][j] = __uint_as_float((unsigned)(acc[i][j] >> 32))           + bja[j];
        }

    float s[8], ss[8];
    #pragma unroll
    for (int i = 0; i < 8; i++) {
        s[i]  = val[i][0] + val[i][1] + val[i][2] + val[i][3];
        ss[i] = val[i][0] * val[i][0] + val[i][1] * val[i][1]
              + val[i][2] * val[i][2] + val[i][3] * val[i][3];
    }
    // reduce across the 16 tx lanes (xor masks stay inside each 16-lane half)
    #pragma unroll
    for (int m = 1; m < 16; m <<= 1) {
        #pragma unroll
        for (int i = 0; i < 8; i++) {
            s[i]  += __shfl_xor_sync(0xFFFFFFFFu, s[i],  m);
            ss[i] += __shfl_xor_sync(0xFFFFFFFFu, ss[i], m);
        }
    }

    const float inv64 = 1.0f / 64.0f;
    #pragma unroll
    for (int i = 0; i < 8; i++) {
        float mu  = s[i] * inv64;
        float var = ss[i] * inv64 - mu * mu;
        float rs  = rsqrtf(var + LN_EPS);
        int gn = node_base + 8 * ty + i;
        if (gn < n_nodes) {
            float4 o;
            o.x = (val[i][0] - mu) * rs * gj.x + ej.x;
            o.y = (val[i][1] - mu) * rs * gj.y + ej.y;
            o.z = (val[i][2] - mu) * rs * gj.z + ej.z;
            o.w = (val[i][3] - mu) * rs * gj.w + ej.w;
            out4[(long long)gn * 16 + tx] = o;
        }
    }
}

// ---------------------------------------------------------------------------
// launch
// ---------------------------------------------------------------------------
extern "C" void kernel_launch(void* const* d_in, const int* in_sizes, int n_in,
                              void* d_out, int out_size) {
    const float* x     = (const float*)d_in[0];
    const void*  ei    = d_in[1];
    const float* W     = (const float*)d_in[2];
    const float* b     = (const float*)d_in[3];
    const float* gamma = (const float*)d_in[4];
    const float* beta  = (const float*)d_in[5];
    float* out = (float*)d_out;

    const int n_nodes = in_sizes[0] / D;      // 100000
    const int n_edges = in_sizes[1] / 2;      // 1000000

    // dynamic smem: A (64KB) + W (32KB) = 96KB
    static_assert(128 * 128 * 4 + 128 * 64 * 4 == 98304, "smem layout");
    cudaFuncSetAttribute(gemm_ln_kernel,
                         cudaFuncAttributeMaxDynamicSharedMemorySize, 98304);

    // 0: zero accumulator + parallel dtype detection (block 0)
    int n_words = n_edges / 2;
    if (n_words > 256) n_words = 256;
    const int n_f4 = n_nodes * D / 4;
    zero_detect_kernel<<<1184, 256>>>(n_f4, (const long long*)ei, n_words, n_nodes);

    // 1: scatter (16 lanes/edge, vectorized red.v4)
    scatter_kernel<<<2368, 256>>>((const float4*)x, ei, n_edges);

    // 2: fused GEMM + LayerNorm (8x4 node-packed tile, NO RMW)
    int gemm_blocks = (n_nodes + TILE_N - 1) / TILE_N;
    gemm_ln_kernel<<<gemm_blocks, NTHR, 98304>>>(
        (const float4*)x, W, b, gamma, beta, (float4*)out, n_nodes);
}